// round 3
// baseline (speedup 1.0000x reference)
#include <cuda_runtime.h>
#include <math.h>
#include <stdint.h>

#define BB 8
#define NN 2048
#define FD 256
#define KK 205
#define KMAX 256
#define LMAX 128

// output layout (float32): x_c | coarse | S | topi
#define XC_OFF ((size_t)0)
#define CO_OFF ((size_t)BB * NN * FD)
#define S_OFF  (CO_OFF + (size_t)BB * NN * NN)
#define TI_OFF (S_OFF + (size_t)BB * NN * NN)

// ---- scratch (static device globals; no allocation) ----
__device__ float g_dg[BB][NN];       // (1 + rowsum)^-0.5   (== d == dg)
__device__ float g_rowfac[BB][NN];   // dg * mask(rowsum>0)
__device__ float g_y[BB][NN];        // x @ W
__device__ float g_alpha[BB][NN];
__device__ float g_ca[BB][NN];       // cut_alpha
__device__ float g_invr[BB][NN];     // 1 / max(row L1 of S_pre, 1e-12)
__device__ int   g_colidx[BB][NN];   // m -> compact support slot j, or -1
__device__ int   g_sup[BB][KMAX];    // support column list (ascending m)
__device__ int   g_nsup[BB];
__device__ int   g_adjcnt[BB][NN];   // nnz per adj row
__device__ int   g_adjk[BB][NN][LMAX];
__device__ float g_adja[BB][NN][LMAX];
__device__ float g_Sc[BB][NN][KMAX]; // S compacted to support columns
__device__ float g_T[BB][NN][KMAX];  // adj @ Sc

// ---------------- kA: single adj pass: rowsum + nnz extraction + y = x@W ----
__global__ void kA_scan(const float* __restrict__ x,
                        const float* __restrict__ adj,
                        const float* __restrict__ W) {
    int bid = blockIdx.x;
    int b = bid >> 11, n = bid & (NN - 1);
    int t = threadIdx.x;
    const float4* arow = (const float4*)(adj + ((size_t)b * NN + n) * NN);
    float loc_a[8]; int loc_k[8];
    int cnt = 0;
    float s = 0.f;
    #pragma unroll
    for (int q = 0; q < 2; q++) {
        float4 v = arow[t * 2 + q];
        int kbase = t * 8 + q * 4;
        float va[4] = {v.x, v.y, v.z, v.w};
        #pragma unroll
        for (int i = 0; i < 4; i++) {
            float a = va[i];
            s += a;
            if (a != 0.f) { loc_a[cnt] = a; loc_k[cnt] = kbase + i; cnt++; }
        }
    }
    float yv = x[((size_t)b * NN + n) * FD + t] * W[t];

    __shared__ int sc[256];
    __shared__ float sh[256], sh2[256];
    sc[t] = cnt; sh[t] = s; sh2[t] = yv;
    __syncthreads();
    // inclusive scan of counts (order-preserving)
    for (int d = 1; d < 256; d <<= 1) {
        int v = (t >= d) ? sc[t - d] : 0;
        __syncthreads();
        sc[t] += v;
        __syncthreads();
    }
    int off = sc[t] - cnt;
    for (int i = 0; i < cnt; i++) {
        int p = off + i;
        if (p < LMAX) { g_adjk[b][n][p] = loc_k[i]; g_adja[b][n][p] = loc_a[i]; }
    }
    if (t == 255) {
        int total = sc[255];
        g_adjcnt[b][n] = (total > LMAX) ? LMAX : total;
    }
    for (int st = 128; st > 0; st >>= 1) {
        if (t < st) { sh[t] += sh[t + st]; sh2[t] += sh2[t + st]; }
        __syncthreads();
    }
    if (t == 0) {
        float rs = sh[0];
        float dg = rsqrtf(1.0f + rs);
        g_dg[b][n] = dg;
        g_rowfac[b][n] = (rs > 0.f) ? dg : 0.f;
        g_y[b][n] = sh2[0];
    }
}

// ---------------- kB: alpha = sigmoid(z^2), z from CSR matvec --------------
__global__ void kB_alpha(const float* __restrict__ bias) {
    int gw = blockIdx.x * 8 + (threadIdx.x >> 5);   // one warp per row
    int b = gw >> 11, n = gw & (NN - 1);
    int lane = threadIdx.x & 31;
    int cnt = g_adjcnt[b][n];
    float dot = 0.f;
    for (int i = lane; i < cnt; i += 32) {
        int k = g_adjk[b][n][i];
        dot += g_adja[b][n][i] * g_dg[b][k] * g_y[b][k];
    }
    #pragma unroll
    for (int o = 16; o > 0; o >>= 1) dot += __shfl_down_sync(0xFFFFFFFFu, dot, o);
    if (lane == 0) {
        float dg = g_dg[b][n];
        float z = dg * (dot + dg * g_y[b][n]) + bias[0];
        float zz = z * z;
        g_alpha[b][n] = 1.0f / (1.0f + expf(-zz));
    }
}

// ---------------- k3: top-k sort + cut + support ----------------
__global__ void k3_topk(float* __restrict__ out_topi) {
    int b = blockIdx.x;
    int t = threadIdx.x;  // 1024 threads
    __shared__ unsigned long long key[NN];
    for (int i = t; i < NN; i += 1024) {
        unsigned int vb = __float_as_uint(g_alpha[b][i]); // alpha in (0.5,1] > 0
        key[i] = ((unsigned long long)vb << 11) | (unsigned)(NN - 1 - i);
    }
    __syncthreads();
    // bitonic sort, descending (value desc; tie -> smaller index first)
    for (int k = 2; k <= NN; k <<= 1) {
        for (int j = k >> 1; j > 0; j >>= 1) {
            for (int i = t; i < NN; i += 1024) {
                int ix = i ^ j;
                if (ix > i) {
                    bool desc = ((i & k) == 0);
                    unsigned long long a = key[i], c = key[ix];
                    if (desc ? (a < c) : (a > c)) { key[i] = c; key[ix] = a; }
                }
            }
            __syncthreads();
        }
    }
    if (t < KK) {
        int idx = NN - 1 - (int)(key[t] & 0x7FFull);
        out_topi[b * KK + t] = (float)idx;
    }
    __shared__ float cutsh;
    if (t == 0) cutsh = __uint_as_float((unsigned)(key[KK - 1] >> 11));
    __syncthreads();
    float cut = cutsh;
    // cut_alpha + ordered support compaction
    __shared__ int cnts[1024];
    int m0 = 2 * t, m1 = 2 * t + 1;
    float ca0 = fmaxf(g_alpha[b][m0] + 1e-07f - cut, 0.f);
    float ca1 = fmaxf(g_alpha[b][m1] + 1e-07f - cut, 0.f);
    g_ca[b][m0] = ca0; g_ca[b][m1] = ca1;
    int c = (ca0 > 0.f) + (ca1 > 0.f);
    cnts[t] = c;
    __syncthreads();
    for (int d = 1; d < 1024; d <<= 1) {
        int v = (t >= d) ? cnts[t - d] : 0;
        __syncthreads();
        cnts[t] += v;
        __syncthreads();
    }
    int off = cnts[t] - c;
    if (t == 1023) {
        int ns = cnts[1023];
        g_nsup[b] = (ns > KMAX) ? KMAX : ns;
    }
    int j = off;
    if (ca0 > 0.f) {
        if (j < KMAX) g_sup[b][j] = m0;
        g_colidx[b][m0] = (j < KMAX) ? j : -1;
        j++;
    } else g_colidx[b][m0] = -1;
    if (ca1 > 0.f) {
        if (j < KMAX) g_sup[b][j] = m1;
        g_colidx[b][m1] = (j < KMAX) ? j : -1;
    } else g_colidx[b][m1] = -1;
}

// ---------------- k4: build S (dense out + compact Sc) + invr ----------------
__global__ void k4_buildS(float* __restrict__ S_out) {
    int bid = blockIdx.x;
    int b = bid >> 11, n = bid & (NN - 1);
    int t = threadIdx.x;
    g_Sc[b][n][t] = 0.f;  // zero compacted row
    __shared__ int diagp;
    __shared__ float red[256];
    if (t == 0) diagp = 0;
    __syncthreads();                      // init visible before any set
    int cnt = g_adjcnt[b][n];
    float rf = g_rowfac[b][n];
    int kk = -1; float aval = 0.f;
    if (t < cnt) {
        kk = g_adjk[b][n][t];
        aval = g_adja[b][n][t];
        if (kk == n) diagp = 1;
    }
    __syncthreads();
    if (t < cnt && kk == n) aval += 1.0f;            // A_hat = adj + I
    if (t == cnt && !diagp) { kk = n; aval = 1.0f; } // virtual diagonal
    float wv = 0.f;
    if (kk >= 0) wv = rf * aval * g_dg[b][kk] * g_ca[b][kk];
    red[t] = wv;
    __syncthreads();
    for (int st = 128; st > 0; st >>= 1) {
        if (t < st) red[t] += red[t + st];
        __syncthreads();
    }
    float invr = 1.0f / fmaxf(red[0], 1e-12f);
    if (t == 0) g_invr[b][n] = invr;
    if (kk >= 0) {
        float val = wv * invr;
        S_out[((size_t)b * NN + n) * NN + kk] = val;
        int j = g_colidx[b][kk];
        if (j >= 0) g_Sc[b][n][j] = val;
    }
}

// ---------------- k5: T = adj @ Sc (CSR SpMM) ----------------
__global__ void k5_T() {
    int bid = blockIdx.x;
    int b = bid >> 11, n = bid & (NN - 1);
    int t = threadIdx.x;
    int cnt = g_adjcnt[b][n];
    int ns = g_nsup[b];
    __shared__ int sk[LMAX];
    __shared__ float sa[LMAX];
    for (int i = t; i < cnt; i += 256) { sk[i] = g_adjk[b][n][i]; sa[i] = g_adja[b][n][i]; }
    __syncthreads();
    float acc = 0.f;
    if (t < ns) {
        int i = 0;
        for (; i + 4 <= cnt; i += 4) {
            float p0 = g_Sc[b][sk[i]][t];
            float p1 = g_Sc[b][sk[i + 1]][t];
            float p2 = g_Sc[b][sk[i + 2]][t];
            float p3 = g_Sc[b][sk[i + 3]][t];
            acc += sa[i] * p0 + sa[i + 1] * p1 + sa[i + 2] * p2 + sa[i + 3] * p3;
        }
        for (; i < cnt; i++) acc += sa[i] * g_Sc[b][sk[i]][t];
    }
    g_T[b][n][t] = acc;
}

// shared helper: load column-m weights of S into shared (pattern = adjlist[m] (+diag))
__device__ __forceinline__ int load_col_weights(int b, int m, int t,
                                                int* sk, float* sw, int* diagp) {
    int cnt = g_adjcnt[b][m];
    float colscale = g_dg[b][m] * g_ca[b][m];
    if (t == 0) *diagp = 0;
    __syncthreads();
    int kk = -1; float a = 0.f;
    if (t < cnt) {
        kk = g_adjk[b][m][t];
        a = g_adja[b][m][t];
        if (kk == m) *diagp = 1;
    }
    __syncthreads();
    if (t < cnt) {
        if (kk == m) a += 1.0f;
        sk[t] = kk;
        sw[t] = g_rowfac[b][kk] * a * colscale * g_invr[b][kk];
    }
    int tot = cnt + ((*diagp) ? 0 : 1);
    if (!(*diagp) && t == 0) {
        sk[cnt] = m;
        sw[cnt] = g_rowfac[b][m] * colscale * g_invr[b][m];
    }
    __syncthreads();
    return tot;
}

// ---------------- k6: x_c = S^T x, only support rows ----------------
__global__ void k6_xc(float* __restrict__ xc, const float* __restrict__ x) {
    int j = blockIdx.x, b = blockIdx.y;
    if (j >= g_nsup[b]) return;
    int m = g_sup[b][j];
    int t = threadIdx.x;
    __shared__ int sk[LMAX + 1];
    __shared__ float sw[LMAX + 1];
    __shared__ int diagp;
    int tot = load_col_weights(b, m, t, sk, sw, &diagp);
    float acc = 0.f;
    for (int i = 0; i < tot; i++)
        acc += sw[i] * x[((size_t)b * NN + sk[i]) * FD + t];
    xc[((size_t)b * NN + m) * FD + t] = acc;
}

// ---------------- k7: coarse = S^T T, floor-quantized scatter ----------------
__global__ void k7_coarse(float* __restrict__ coarse) {
    int j = blockIdx.x, b = blockIdx.y;
    int ns = g_nsup[b];
    if (j >= ns) return;
    int m = g_sup[b][j];
    int t = threadIdx.x;
    __shared__ int sk[LMAX + 1];
    __shared__ float sw[LMAX + 1];
    __shared__ int diagp;
    int tot = load_col_weights(b, m, t, sk, sw, &diagp);
    if (t < ns) {
        float acc = 0.f;
        for (int i = 0; i < tot; i++)
            acc += sw[i] * g_T[b][sk[i]][t];
        float q = floorf(acc * 10000.0f) / 10000.0f;
        int l = g_sup[b][t];
        coarse[((size_t)b * NN + m) * NN + l] = q;
    }
}

extern "C" void kernel_launch(void* const* d_in, const int* in_sizes, int n_in,
                              void* d_out, int out_size) {
    const float* x    = (const float*)d_in[0];
    const float* adj  = (const float*)d_in[1];
    const float* W    = (const float*)d_in[2];
    const float* bias = (const float*)d_in[3];
    float* out = (float*)d_out;

    cudaMemsetAsync(d_out, 0, (size_t)out_size * sizeof(float), 0);

    kA_scan<<<BB * NN, 256>>>(x, adj, W);
    kB_alpha<<<BB * NN / 8, 256>>>(bias);
    k3_topk<<<BB, 1024>>>(out + TI_OFF);
    k4_buildS<<<BB * NN, 256>>>(out + S_OFF);
    k5_T<<<BB * NN, 256>>>();
    k6_xc<<<dim3(KMAX, BB), 256>>>(out + XC_OFF, x);
    k7_coarse<<<dim3(KMAX, BB), 256>>>(out + CO_OFF);
}

// round 4
// speedup vs baseline: 1.0103x; 1.0103x over previous
#include <cuda_runtime.h>
#include <math.h>
#include <stdint.h>

#define BB 8
#define NN 2048
#define FD 256
#define KK 205
#define KMAX 256
#define LMAX 128
#define FULLM 0xFFFFFFFFu

// output layout (float32): x_c | coarse | S | topi
#define XC_OFF ((size_t)0)
#define CO_OFF ((size_t)BB * NN * FD)
#define S_OFF  (CO_OFF + (size_t)BB * NN * NN)
#define TI_OFF (S_OFF + (size_t)BB * NN * NN)

// ---- scratch (static device globals; no allocation) ----
__device__ float g_dg[BB][NN];
__device__ float g_rowfac[BB][NN];
__device__ float g_y[BB][NN];
__device__ float g_alpha[BB][NN];
__device__ float g_ca[BB][NN];
__device__ float g_invr[BB][NN];
__device__ int   g_colidx[BB][NN];
__device__ int   g_sup[BB][KMAX];
__device__ int   g_nsup[BB];
__device__ int   g_adjcnt[BB][NN];
__device__ int   g_adjk[BB][NN][LMAX];
__device__ float g_adja[BB][NN][LMAX];
__device__ float g_Sc[BB][NN][KMAX];
__device__ float g_T[BB][NN][KMAX];

// ---------------- kA: single adj pass: rowsum + nnz extraction + y = x@W ----
__global__ void kA_scan(const float* __restrict__ x,
                        const float* __restrict__ adj,
                        const float* __restrict__ W) {
    int bid = blockIdx.x;
    int b = bid >> 11, n = bid & (NN - 1);
    int t = threadIdx.x;
    int wid = t >> 5, lane = t & 31;
    const float4* arow = (const float4*)(adj + ((size_t)b * NN + n) * NN);
    float loc_a[8]; int loc_k[8];
    int cnt = 0;
    float s = 0.f;
    #pragma unroll
    for (int q = 0; q < 2; q++) {
        float4 v = arow[t * 2 + q];
        int kbase = t * 8 + q * 4;
        float va[4] = {v.x, v.y, v.z, v.w};
        #pragma unroll
        for (int i = 0; i < 4; i++) {
            float a = va[i];
            s += a;
            if (a != 0.f) { loc_a[cnt] = a; loc_k[cnt] = kbase + i; cnt++; }
        }
    }
    float yv = x[((size_t)b * NN + n) * FD + t] * W[t];

    // warp-level inclusive scan of cnt
    int pre = cnt;
    #pragma unroll
    for (int o = 1; o < 32; o <<= 1) {
        int v = __shfl_up_sync(FULLM, pre, o);
        if (lane >= o) pre += v;
    }
    // warp reductions of s, yv
    float ssum = s, ysum = yv;
    #pragma unroll
    for (int o = 16; o > 0; o >>= 1) {
        ssum += __shfl_down_sync(FULLM, ssum, o);
        ysum += __shfl_down_sync(FULLM, ysum, o);
    }
    __shared__ int wtot[8];
    __shared__ float ws[8], wy[8];
    if (lane == 31) wtot[wid] = pre;
    if (lane == 0) { ws[wid] = ssum; wy[wid] = ysum; }
    __syncthreads();
    int base = 0;
    #pragma unroll
    for (int w = 0; w < 8; w++) base += (w < wid) ? wtot[w] : 0;
    int off = base + pre - cnt;
    #pragma unroll
    for (int i = 0; i < 8; i++) {
        if (i < cnt) {
            int p = off + i;
            if (p < LMAX) { g_adjk[b][n][p] = loc_k[i]; g_adja[b][n][p] = loc_a[i]; }
        }
    }
    if (t == 0) {
        int total = wtot[0] + wtot[1] + wtot[2] + wtot[3]
                  + wtot[4] + wtot[5] + wtot[6] + wtot[7];
        g_adjcnt[b][n] = (total > LMAX) ? LMAX : total;
        float rs = ((ws[0] + ws[1]) + (ws[2] + ws[3])) + ((ws[4] + ws[5]) + (ws[6] + ws[7]));
        float dg = rsqrtf(1.0f + rs);
        g_dg[b][n] = dg;
        g_rowfac[b][n] = (rs > 0.f) ? dg : 0.f;
        g_y[b][n] = ((wy[0] + wy[1]) + (wy[2] + wy[3])) + ((wy[4] + wy[5]) + (wy[6] + wy[7]));
    }
}

// ---------------- kB: alpha = sigmoid(z^2) ----------------
__global__ void kB_alpha(const float* __restrict__ bias) {
    int gw = blockIdx.x * 8 + (threadIdx.x >> 5);
    int b = gw >> 11, n = gw & (NN - 1);
    int lane = threadIdx.x & 31;
    int cnt = g_adjcnt[b][n];
    float dot = 0.f;
    for (int i = lane; i < cnt; i += 32) {
        int k = g_adjk[b][n][i];
        dot += g_adja[b][n][i] * g_dg[b][k] * g_y[b][k];
    }
    #pragma unroll
    for (int o = 16; o > 0; o >>= 1) dot += __shfl_down_sync(FULLM, dot, o);
    if (lane == 0) {
        float dg = g_dg[b][n];
        float z = dg * (dot + dg * g_y[b][n]) + bias[0];
        float zz = z * z;
        g_alpha[b][n] = 1.0f / (1.0f + expf(-zz));
    }
}

// ---------------- k3: top-k sort + cut + support ----------------
__global__ void k3_topk(float* __restrict__ out_topi) {
    int b = blockIdx.x;
    int t = threadIdx.x;  // 1024
    __shared__ unsigned long long key[NN];
    for (int i = t; i < NN; i += 1024) {
        unsigned int vb = __float_as_uint(g_alpha[b][i]);
        key[i] = ((unsigned long long)vb << 11) | (unsigned)(NN - 1 - i);
    }
    __syncthreads();
    for (int k = 2; k <= NN; k <<= 1) {
        for (int j = k >> 1; j > 0; j >>= 1) {
            for (int i = t; i < NN; i += 1024) {
                int ix = i ^ j;
                if (ix > i) {
                    bool desc = ((i & k) == 0);
                    unsigned long long a = key[i], c = key[ix];
                    if (desc ? (a < c) : (a > c)) { key[i] = c; key[ix] = a; }
                }
            }
            __syncthreads();
        }
    }
    if (t < KK) {
        int idx = NN - 1 - (int)(key[t] & 0x7FFull);
        out_topi[b * KK + t] = (float)idx;
    }
    __shared__ float cutsh;
    if (t == 0) cutsh = __uint_as_float((unsigned)(key[KK - 1] >> 11));
    __syncthreads();
    float cut = cutsh;
    __shared__ int cnts[1024];
    int m0 = 2 * t, m1 = 2 * t + 1;
    float ca0 = fmaxf(g_alpha[b][m0] + 1e-07f - cut, 0.f);
    float ca1 = fmaxf(g_alpha[b][m1] + 1e-07f - cut, 0.f);
    g_ca[b][m0] = ca0; g_ca[b][m1] = ca1;
    int c = (ca0 > 0.f) + (ca1 > 0.f);
    cnts[t] = c;
    __syncthreads();
    for (int d = 1; d < 1024; d <<= 1) {
        int v = (t >= d) ? cnts[t - d] : 0;
        __syncthreads();
        cnts[t] += v;
        __syncthreads();
    }
    int off = cnts[t] - c;
    if (t == 1023) {
        int ns = cnts[1023];
        g_nsup[b] = (ns > KMAX) ? KMAX : ns;
    }
    int j = off;
    if (ca0 > 0.f) {
        if (j < KMAX) g_sup[b][j] = m0;
        g_colidx[b][m0] = (j < KMAX) ? j : -1;
        j++;
    } else g_colidx[b][m0] = -1;
    if (ca1 > 0.f) {
        if (j < KMAX) g_sup[b][j] = m1;
        g_colidx[b][m1] = (j < KMAX) ? j : -1;
    } else g_colidx[b][m1] = -1;
}

// ---------------- k4: build S dense row + compact Sc + invr ----------------
__global__ void k4_buildS(float* __restrict__ S_out) {
    int bid = blockIdx.x;
    int b = bid >> 11, n = bid & (NN - 1);
    int t = threadIdx.x;
    int wid = t >> 5, lane = t & 31;
    __shared__ float srow[NN];          // dense S row (8 KB)
    __shared__ float wsum[8];
    __shared__ int diagp;
    // zero dense row + compacted row
    float4* sr4 = (float4*)srow;
    sr4[t] = make_float4(0.f, 0.f, 0.f, 0.f);
    sr4[t + 256] = make_float4(0.f, 0.f, 0.f, 0.f);
    g_Sc[b][n][t] = 0.f;
    if (t == 0) diagp = 0;
    __syncthreads();
    int cnt = g_adjcnt[b][n];
    float rf = g_rowfac[b][n];
    int kk = -1; float aval = 0.f;
    if (t < cnt) {
        kk = g_adjk[b][n][t];
        aval = g_adja[b][n][t];
        if (kk == n) diagp = 1;
    }
    __syncthreads();
    if (t < cnt && kk == n) aval += 1.0f;            // A_hat = adj + I
    if (t == cnt && !diagp) { kk = n; aval = 1.0f; } // virtual diagonal
    float wv = 0.f;
    if (kk >= 0) wv = rf * aval * g_dg[b][kk] * g_ca[b][kk];
    // block L1 sum via warp shuffles
    float r = wv;
    #pragma unroll
    for (int o = 16; o > 0; o >>= 1) r += __shfl_down_sync(FULLM, r, o);
    if (lane == 0) wsum[wid] = r;
    __syncthreads();
    float tot = ((wsum[0] + wsum[1]) + (wsum[2] + wsum[3]))
              + ((wsum[4] + wsum[5]) + (wsum[6] + wsum[7]));
    float invr = 1.0f / fmaxf(tot, 1e-12f);
    if (t == 0) g_invr[b][n] = invr;
    if (kk >= 0) {
        float val = wv * invr;
        srow[kk] = val;
        int j = g_colidx[b][kk];
        if (j >= 0) g_Sc[b][n][j] = val;
    }
    __syncthreads();
    // dense streaming write of the full row
    float4* drow = (float4*)(S_out + ((size_t)b * NN + n) * NN);
    drow[t] = sr4[t];
    drow[t + 256] = sr4[t + 256];
}

// ---------------- k5: T = adj @ Sc (CSR SpMM) ----------------
__global__ void k5_T() {
    int bid = blockIdx.x;
    int b = bid >> 11, n = bid & (NN - 1);
    int t = threadIdx.x;
    int cnt = g_adjcnt[b][n];
    int ns = g_nsup[b];
    __shared__ int sk[LMAX];
    __shared__ float sa[LMAX];
    if (t < cnt) { sk[t] = g_adjk[b][n][t]; sa[t] = g_adja[b][n][t]; }
    __syncthreads();
    float acc = 0.f;
    if (t < ns) {
        int i = 0;
        for (; i + 4 <= cnt; i += 4) {
            float p0 = g_Sc[b][sk[i]][t];
            float p1 = g_Sc[b][sk[i + 1]][t];
            float p2 = g_Sc[b][sk[i + 2]][t];
            float p3 = g_Sc[b][sk[i + 3]][t];
            acc += sa[i] * p0 + sa[i + 1] * p1 + sa[i + 2] * p2 + sa[i + 3] * p3;
        }
        for (; i < cnt; i++) acc += sa[i] * g_Sc[b][sk[i]][t];
    }
    g_T[b][n][t] = acc;
}

// helper: weights of S column m (pattern = adjlist[m] (+diag), symmetric adj)
__device__ __forceinline__ int load_col_weights(int b, int m, int t,
                                                int* sk, float* sw, int* diagp) {
    int cnt = g_adjcnt[b][m];
    float colscale = g_dg[b][m] * g_ca[b][m];
    if (t == 0) *diagp = 0;
    __syncthreads();
    int kk = -1; float a = 0.f;
    if (t < cnt) {
        kk = g_adjk[b][m][t];
        a = g_adja[b][m][t];
        if (kk == m) *diagp = 1;
    }
    __syncthreads();
    if (t < cnt) {
        if (kk == m) a += 1.0f;
        sk[t] = kk;
        sw[t] = g_rowfac[b][kk] * a * colscale * g_invr[b][kk];
    }
    int tot = cnt + ((*diagp) ? 0 : 1);
    if (!(*diagp) && t == 0) {
        sk[cnt] = m;
        sw[cnt] = g_rowfac[b][m] * colscale * g_invr[b][m];
    }
    __syncthreads();
    return tot;
}

// ---------------- k6: x_c = S^T x, dense rows (zeros for non-support) -------
__global__ void k6_xc(float* __restrict__ xc, const float* __restrict__ x) {
    int m = blockIdx.x, b = blockIdx.y;
    int t = threadIdx.x;
    float* orow = xc + ((size_t)b * NN + m) * FD;
    if (g_colidx[b][m] < 0) { orow[t] = 0.f; return; }
    __shared__ int sk[LMAX + 1];
    __shared__ float sw[LMAX + 1];
    __shared__ int diagp;
    int tot = load_col_weights(b, m, t, sk, sw, &diagp);
    float acc = 0.f;
    for (int i = 0; i < tot; i++)
        acc += sw[i] * x[((size_t)b * NN + sk[i]) * FD + t];
    orow[t] = acc;
}

// ---------------- k7: coarse = S^T T, dense rows ----------------
__global__ void k7_coarse(float* __restrict__ coarse) {
    int m = blockIdx.x, b = blockIdx.y;
    int t = threadIdx.x;
    float4* orow = (float4*)(coarse + ((size_t)b * NN + m) * NN);
    int cidx = g_colidx[b][m];
    if (cidx < 0) {   // zero row
        float4 z = make_float4(0.f, 0.f, 0.f, 0.f);
        orow[t] = z; orow[t + 256] = z;
        return;
    }
    int ns = g_nsup[b];
    __shared__ float srow[NN];
    __shared__ int sk[LMAX + 1];
    __shared__ float sw[LMAX + 1];
    __shared__ int diagp;
    float4* sr4 = (float4*)srow;
    sr4[t] = make_float4(0.f, 0.f, 0.f, 0.f);
    sr4[t + 256] = make_float4(0.f, 0.f, 0.f, 0.f);
    int tot = load_col_weights(b, m, t, sk, sw, &diagp);
    if (t < ns) {
        float acc = 0.f;
        for (int i = 0; i < tot; i++)
            acc += sw[i] * g_T[b][sk[i]][t];
        float q = floorf(acc * 10000.0f) / 10000.0f;
        srow[g_sup[b][t]] = q;
    }
    __syncthreads();
    orow[t] = sr4[t];
    orow[t + 256] = sr4[t + 256];
}

extern "C" void kernel_launch(void* const* d_in, const int* in_sizes, int n_in,
                              void* d_out, int out_size) {
    const float* x    = (const float*)d_in[0];
    const float* adj  = (const float*)d_in[1];
    const float* W    = (const float*)d_in[2];
    const float* bias = (const float*)d_in[3];
    float* out = (float*)d_out;

    kA_scan<<<BB * NN, 256>>>(x, adj, W);
    kB_alpha<<<BB * NN / 8, 256>>>(bias);
    k3_topk<<<BB, 1024>>>(out + TI_OFF);
    k4_buildS<<<BB * NN, 256>>>(out + S_OFF);
    k5_T<<<BB * NN, 256>>>();
    k6_xc<<<dim3(NN, BB), 256>>>(out + XC_OFF, x);
    k7_coarse<<<dim3(NN, BB), 256>>>(out + CO_OFF);
}